// round 15
// baseline (speedup 1.0000x reference)
#include <cuda_runtime.h>
#include <cuda_bf16.h>
#include <cstdint>

#define T_STEPS 512
#define BATCH   32
#define DIM     1024
#define NS      64
#define M_TOT   (T_STEPS * BATCH)   // 16384

// ---------------------------------------------------------------------------
// Device scratch
// ---------------------------------------------------------------------------
__device__ __align__(16) float  g_proj[(size_t)M_TOT * 256];   // [m][{k,q,v,ax}x64]
__device__ __align__(16) float4 g_kk[M_TOT];
__device__ __align__(16) __nv_bfloat16 g_Wh[256 * DIM];        // rows: k,q,v,ax
__device__ __align__(16) __nv_bfloat16 g_Wl[256 * DIM];

// ---------------------------------------------------------------------------
// helpers
// ---------------------------------------------------------------------------
__device__ __forceinline__ uint32_t smem_u32(const void* p) {
    uint32_t a;
    asm("{ .reg .u64 t; cvta.to.shared.u64 t, %1; cvt.u32.u64 %0, t; }" : "=r"(a) : "l"(p));
    return a;
}
__device__ __forceinline__ uint32_t bfpack(float hi_elem, float lo_elem) {
    uint32_t r;
    asm("cvt.rn.bf16x2.f32 %0, %1, %2;" : "=r"(r) : "f"(hi_elem), "f"(lo_elem));
    return r;
}
__device__ __forceinline__ uint32_t swoff(int row, int unit) {
    return (uint32_t)(row * 64 + ((unit ^ ((row >> 1) & 3)) << 4));
}
__device__ __forceinline__ void cp16(uint32_t dst, const void* src) {
    asm volatile("cp.async.cg.shared.global [%0], [%1], 16;" :: "r"(dst), "l"(src) : "memory");
}
__device__ __forceinline__ void ldsm4(uint32_t* r, uint32_t a) {
    asm volatile("ldmatrix.sync.aligned.m8n8.x4.shared.b16 {%0,%1,%2,%3}, [%4];"
                 : "=r"(r[0]), "=r"(r[1]), "=r"(r[2]), "=r"(r[3]) : "r"(a));
}
__device__ __forceinline__ void ldsm2(uint32_t* r, uint32_t a) {
    asm volatile("ldmatrix.sync.aligned.m8n8.x2.shared.b16 {%0,%1}, [%2];"
                 : "=r"(r[0]), "=r"(r[1]) : "r"(a));
}
__device__ __forceinline__ void mma16816(float* c, const uint32_t* a, const uint32_t* b) {
    asm volatile(
        "mma.sync.aligned.m16n8k16.row.col.f32.bf16.bf16.f32 "
        "{%0,%1,%2,%3}, {%4,%5,%6,%7}, {%8,%9}, {%0,%1,%2,%3};"
        : "+f"(c[0]), "+f"(c[1]), "+f"(c[2]), "+f"(c[3])
        : "r"(a[0]), "r"(a[1]), "r"(a[2]), "r"(a[3]), "r"(b[0]), "r"(b[1]));
}

// ---------------------------------------------------------------------------
// Weight prep: split 4x[64,1024] fp32 into bf16 hi/lo, row order k,q,v,ax
// ---------------------------------------------------------------------------
__global__ __launch_bounds__(256) void prep_w(
    const float* __restrict__ Wk, const float* __restrict__ Wq,
    const float* __restrict__ Wv, const float* __restrict__ Wa)
{
    int idx = blockIdx.x * 256 + threadIdx.x;
    int r = idx >> 8, c4 = idx & 255;
    const float* W = (r < 64) ? Wk : (r < 128) ? Wq : (r < 192) ? Wv : Wa;
    float4 v = ((const float4*)(W + (size_t)(r & 63) * DIM))[c4];
    uint32_t h01 = bfpack(v.y, v.x);
    uint32_t h23 = bfpack(v.w, v.z);
    float l0 = v.x - __uint_as_float(h01 << 16);
    float l1 = v.y - __uint_as_float(h01 & 0xffff0000u);
    float l2 = v.z - __uint_as_float(h23 << 16);
    float l3 = v.w - __uint_as_float(h23 & 0xffff0000u);
    ((uint2*)g_Wh)[idx] = make_uint2(h01, h23);
    ((uint2*)g_Wl)[idx] = make_uint2(bfpack(l1, l0), bfpack(l3, l2));
}

// ---------------------------------------------------------------------------
// Tensor-core projection GEMM (mma.sync bf16x3) — unchanged (R7, passed)
// ---------------------------------------------------------------------------
#define STAGE_BYTES 49152
#define GEMM_SMEM   (2 * STAGE_BYTES)

__global__ __launch_bounds__(512) void proj_gemm_mma(const float* __restrict__ X)
{
    extern __shared__ char sm[];
    const uint32_t sb = smem_u32(sm);
    const int tid  = threadIdx.x;
    const int lane = tid & 31;
    const int wid  = tid >> 5;
    const int wm   = wid & 3;
    const int wn   = wid >> 2;
    const int m0   = blockIdx.x * 128;

    float c[2][8][4];
    #pragma unroll
    for (int i = 0; i < 2; i++)
        #pragma unroll
        for (int j = 0; j < 8; j++)
            #pragma unroll
            for (int q = 0; q < 4; q++) c[i][j][q] = 0.f;

    const int xrow = tid >> 2, xu = tid & 3;
    const int wp   = tid >> 8, wrow = tid & 255;

    auto issueW = [&](int ch, int s) {
        const __nv_bfloat16* src = (wp ? g_Wl : g_Wh) + (size_t)wrow * DIM + ch * 32;
        uint32_t dbase = sb + s * STAGE_BYTES + 16384 + wp * 16384;
        #pragma unroll
        for (int u = 0; u < 4; u++) cp16(dbase + swoff(wrow, u), src + u * 8);
        asm volatile("cp.async.commit_group;" ::: "memory");
    };
    float4 xa, xb;
    auto loadX = [&](int ch) {
        const float* p = X + (size_t)(m0 + xrow) * DIM + ch * 32 + xu * 8;
        xa = *(const float4*)p;
        xb = *(const float4*)(p + 4);
    };
    auto stsX = [&](int s) {
        uint32_t h01 = bfpack(xa.y, xa.x), h23 = bfpack(xa.w, xa.z);
        uint32_t h45 = bfpack(xb.y, xb.x), h67 = bfpack(xb.w, xb.z);
        float l0 = xa.x - __uint_as_float(h01 << 16);
        float l1 = xa.y - __uint_as_float(h01 & 0xffff0000u);
        float l2 = xa.z - __uint_as_float(h23 << 16);
        float l3 = xa.w - __uint_as_float(h23 & 0xffff0000u);
        float l4 = xb.x - __uint_as_float(h45 << 16);
        float l5 = xb.y - __uint_as_float(h45 & 0xffff0000u);
        float l6 = xb.z - __uint_as_float(h67 << 16);
        float l7 = xb.w - __uint_as_float(h67 & 0xffff0000u);
        uint32_t off = s * STAGE_BYTES + swoff(xrow, xu);
        *(uint4*)(sm + off)        = make_uint4(h01, h23, h45, h67);
        *(uint4*)(sm + off + 8192) = make_uint4(bfpack(l1, l0), bfpack(l3, l2),
                                                bfpack(l5, l4), bfpack(l7, l6));
    };

    issueW(0, 0);
    loadX(0);

    for (int ch = 0; ch < 32; ch++) {
        const int s = ch & 1;
        asm volatile("cp.async.wait_group 0;" ::: "memory");
        stsX(s);
        if (ch + 1 < 32) { issueW(ch + 1, s ^ 1); loadX(ch + 1); }
        __syncthreads();

        const uint32_t st = sb + s * STAGE_BYTES;
        #pragma unroll
        for (int kt = 0; kt < 2; kt++) {
            uint32_t ah[2][4], al[2][4];
            #pragma unroll
            for (int mt = 0; mt < 2; mt++) {
                uint32_t aoff = swoff(wm * 32 + mt * 16 + (lane & 15), kt * 2 + (lane >> 4));
                ldsm4(ah[mt], st + aoff);
                ldsm4(al[mt], st + 8192 + aoff);
            }
            #pragma unroll
            for (int nt = 0; nt < 8; nt++) {
                uint32_t boff = swoff(wn * 64 + nt * 8 + (lane & 7),
                                      kt * 2 + ((lane >> 3) & 1));
                uint32_t bh[2], bl[2];
                ldsm2(bh, st + 16384 + boff);
                ldsm2(bl, st + 32768 + boff);
                mma16816(c[0][nt], ah[0], bh);
                mma16816(c[1][nt], ah[1], bh);
                mma16816(c[0][nt], al[0], bh);
                mma16816(c[1][nt], al[1], bh);
                mma16816(c[0][nt], ah[0], bl);
                mma16816(c[1][nt], ah[1], bl);
            }
        }
        __syncthreads();
    }

    #pragma unroll
    for (int mt = 0; mt < 2; mt++) {
        #pragma unroll
        for (int nt = 0; nt < 8; nt++) {
            int m = m0 + wm * 32 + mt * 16 + (lane >> 2);
            int n = wn * 64 + nt * 8 + (lane & 3) * 2;
            *(float2*)&g_proj[(size_t)m * 256 + n]       = make_float2(c[mt][nt][0], c[mt][nt][1]);
            *(float2*)&g_proj[(size_t)(m + 8) * 256 + n] = make_float2(c[mt][nt][2], c[mt][nt][3]);
        }
    }
}

// ---------------------------------------------------------------------------
// kk kernel: g_kk[t][b] = {k_t·k_{t+1}, k_t·k_{t+2}, k_t·k_{t+3}, 0}
// ---------------------------------------------------------------------------
__global__ __launch_bounds__(128) void kk_kernel()
{
    int idx = blockIdx.x * 128 + threadIdx.x;
    int t = idx >> 5, b = idx & 31;
    const float4* p0 = (const float4*)(g_proj + (size_t)(t * 32 + b) * 256);
    int t1 = (t + 1 < T_STEPS) ? t + 1 : t;
    int t2 = (t + 2 < T_STEPS) ? t + 2 : t;
    int t3 = (t + 3 < T_STEPS) ? t + 3 : t;
    const float4* p1 = (const float4*)(g_proj + (size_t)(t1 * 32 + b) * 256);
    const float4* p2 = (const float4*)(g_proj + (size_t)(t2 * 32 + b) * 256);
    const float4* p3 = (const float4*)(g_proj + (size_t)(t3 * 32 + b) * 256);
    float a1 = 0.f, a2 = 0.f, a3 = 0.f;
    #pragma unroll
    for (int i = 0; i < 16; i++) {
        float4 k0 = p0[i], q1 = p1[i], q2 = p2[i], q3 = p3[i];
        a1 += k0.x*q1.x + k0.y*q1.y + k0.z*q1.z + k0.w*q1.w;
        a2 += k0.x*q2.x + k0.y*q2.y + k0.z*q2.z + k0.w*q2.w;
        a3 += k0.x*q3.x + k0.y*q3.y + k0.z*q3.z + k0.w*q3.w;
    }
    if (t + 1 >= T_STEPS) a1 = 0.f;
    if (t + 2 >= T_STEPS) a2 = 0.f;
    if (t + 3 >= T_STEPS) a3 = 0.f;
    g_kk[idx] = make_float4(a1, a2, a3, 0.f);
}

// ---------------------------------------------------------------------------
// Scan v7: sigma-affine recurrence, 32 lanes/row (2 cols each), warp = 1 row.
// CTA = 4 rows (128 thr, 4 warps), grid 512 -> 2048 warps (~3.5/SMSP) so
// stalls of one chain are filled by 3 others. k/q/kk staged once per CTA via
// cp.async; v/ax per-row. Steady state LDS-only; 2 syncthreads per 8 steps.
// smem float layout (2752 floats = 11008 B):
//   k:  [0,1536)    3 x 512  (8 steps x 64)
//   q:  [1536,2560) 2 x 512
//   kk: [2560,2624) 2 x 32   (8 x float4)
//   v:  [2624,2688) 2 x 32   (8 steps x 4 rows)
//   ax: [2688,2752) 2 x 32   (pre-shifted +1)
// ---------------------------------------------------------------------------
__global__ __launch_bounds__(128) void scan_kernel(
    const float* __restrict__ S_in,
    const float* __restrict__ d_alpha,
    const float* __restrict__ b_alpha,
    float* __restrict__ out)
{
    __shared__ __align__(16) float sms[2752];

    const int tid  = threadIdx.x;
    const int lane = tid & 31;
    const int w    = tid >> 5;       // warp = row within CTA (0..3)
    const int b    = blockIdx.x >> 4;
    const int rg   = blockIdx.x & 15;   // 16 CTAs per batch
    const int r0   = rg * 4;
    const int row  = r0 + w;
    const int c0   = lane * 2;

    const uint32_t smb = smem_u32(sms);

    auto issue = [&](int B) {
        {   // k(B+2) -> slot (B+2)%3 ; 128 cp16, one per thread
            int ks = (B + 2) % 3;
            int tb = (B + 2) * 8;
            int t = tid >> 4, u = tid & 15;
            int gt = tb + t; if (gt > 511) gt = 511;
            cp16(smb + (uint32_t)(ks * 512 + t * 64 + u * 4) * 4,
                 g_proj + ((size_t)(gt * 32 + b)) * 256 + u * 4);
        }
        if (B >= -1) {
            int ss = (B + 1) & 1;
            int tb = (B + 1) * 8;
            {   // q(B+1) ; 128 cp16
                int t = tid >> 4, u = tid & 15;
                int gt = tb + t; if (gt > 511) gt = 511;
                cp16(smb + (uint32_t)(1536 + ss * 512 + t * 64 + u * 4) * 4,
                     g_proj + ((size_t)(gt * 32 + b)) * 256 + 64 + u * 4);
            }
            if (tid < 8) {          // kk(B+1)
                int gt = tb + tid; if (gt > 511) gt = 511;
                cp16(smb + (uint32_t)(2560 + ss * 32 + tid * 4) * 4,
                     (const float*)&g_kk[gt * 32 + b]);
            } else if (tid < 16) {  // v(B+1): 4 consecutive rows per step
                int t = tid - 8;
                int gt = tb + t; if (gt > 511) gt = 511;
                cp16(smb + (uint32_t)(2624 + ss * 32 + t * 4) * 4,
                     g_proj + ((size_t)(gt * 32 + b)) * 256 + 128 + r0);
            } else if (tid < 24) {  // ax(B+1) shifted +1
                int t = tid - 16;
                int gt = tb + t + 1; if (gt > 511) gt = 511;
                cp16(smb + (uint32_t)(2688 + ss * 32 + t * 4) * 4,
                     g_proj + ((size_t)(gt * 32 + b)) * 256 + 192 + r0);
            }
        }
        asm volatile("cp.async.commit_group;" ::: "memory");
    };

    issue(-2);   // k(0)
    issue(-1);   // k(1) + q(0) + scal(0)

    float S0, S1;
    {
        const float* sp = S_in + ((size_t)b * NS + row) * NS + c0;
        S0 = sp[0]; S1 = sp[1];
    }
    const float da = d_alpha[row];
    const float ba = b_alpha[row];
    const float axb0 = g_proj[(size_t)b * 256 + 192 + row] + ba;   // t=0

    auto red32 = [](float v) {
        v += __shfl_xor_sync(0xffffffffu, v, 1);
        v += __shfl_xor_sync(0xffffffffu, v, 2);
        v += __shfl_xor_sync(0xffffffffu, v, 4);
        v += __shfl_xor_sync(0xffffffffu, v, 8);
        v += __shfl_xor_sync(0xffffffffu, v, 16);
        return v;
    };

    float x, A1, A2, A3;
    float* outp = out + (size_t)b * NS + row;

    for (int B = 0; B < 64; B++) {
        __syncthreads();                                   // consumers done with slot (B+2)%3
        issue(B);                                          // k(B+2), q(B+1), scal(B+1)
        asm volatile("cp.async.wait_group 1;" ::: "memory");
        __syncthreads();                                   // k(B),k(B+1),q(B),scal(B) visible

        const int ck = B % 3, nk = (B + 1) % 3;
        const float* kb  = sms + ck * 512;
        const float* kbn = sms + nk * 512;
        const float* qb  = sms + 1536 + (B & 1) * 512;
        const float* kkb = sms + 2560 + (B & 1) * 32;
        const float* vb  = sms + 2624 + (B & 1) * 32;
        const float* axv = sms + 2688 + (B & 1) * 32;

        if (B == 0) {
            float t0 = 0.f, t1 = 0.f, t2 = 0.f, t3 = 0.f;
            #pragma unroll
            for (int j = 0; j < 2; j++) {
                float s = (j == 0) ? S0 : S1;
                t0 = fmaf(s, kb[0 * 64 + c0 + j], t0);
                t1 = fmaf(s, kb[1 * 64 + c0 + j], t1);
                t2 = fmaf(s, kb[2 * 64 + c0 + j], t2);
                t3 = fmaf(s, kb[3 * 64 + c0 + j], t3);
            }
            float r0v = red32(t0);
            A1 = red32(t1); A2 = red32(t2); A3 = red32(t3);
            x = fmaf(da, r0v, axb0);
        }

        #pragma unroll
        for (int t = 0; t < 8; t++) {
            // ---- LDS reads ----
            float2 kv = *(const float2*)(kb + t * 64 + c0);
            float2 qv = *(const float2*)(qb + t * 64 + c0);
            float2 k4 = *(const float2*)(((t < 4) ? kb + (t + 4) * 64
                                                  : kbn + (t - 4) * 64) + c0);
            const float vc  = vb[t * 4 + w];
            const float axn = axv[t * 4 + w] + ba;         // ax_{t+1}
            float4 kk = *(const float4*)(kkb + t * 4);

            // ---- pre-sigma (independent of sg) ----
            float vk1 = vc * kk.x, vk2 = vc * kk.y, vk3 = vc * kk.z;
            float uA1 = A1 - vk1, uA2 = A2 - vk2, uA3 = A3 - vk3;
            float px  = da * uA1;
            float qx  = fmaf(da, vk1, axn);
            float tj0 = vc * kv.x, tj1 = vc * kv.y;
            float uj0 = S0 - tj0,  uj1 = S1 - tj1;

            // ---- critical chain: sigmoid -> 1 FMA ----
            float sg = __fdividef(1.f, 1.f + __expf(-x));
            x = fmaf(sg, px, qx);

            // ---- sigma-affine updates ----
            A1 = fmaf(sg, uA2, vk2);
            A2 = fmaf(sg, uA3, vk3);
            float s0 = fmaf(sg, uj0, tj0); S0 = s0;
            float s1 = fmaf(sg, uj1, tj1); S1 = s1;
            float h = fmaf(s1, qv.y, s0 * qv.x);
            float d = fmaf(s1, k4.y, s0 * k4.x);
            h += __shfl_xor_sync(0xffffffffu, h, 1);  d += __shfl_xor_sync(0xffffffffu, d, 1);
            h += __shfl_xor_sync(0xffffffffu, h, 2);  d += __shfl_xor_sync(0xffffffffu, d, 2);
            h += __shfl_xor_sync(0xffffffffu, h, 4);  d += __shfl_xor_sync(0xffffffffu, d, 4);
            h += __shfl_xor_sync(0xffffffffu, h, 8);  d += __shfl_xor_sync(0xffffffffu, d, 8);
            h += __shfl_xor_sync(0xffffffffu, h, 16); d += __shfl_xor_sync(0xffffffffu, d, 16);
            A3 = d;                                        // S_t . k_{t+4}

            if (lane == 0) {
                float sh = __fdividef(1.f, 1.f + __expf(-h));
                outp[0] = h * h * sh;                      // h * silu(h)
            }
            outp += BATCH * NS;
        }
    }

    // S_final
    float* sf = out + (size_t)T_STEPS * BATCH * NS + ((size_t)b * NS + row) * NS + c0;
    *(float2*)sf = make_float2(S0, S1);
}

// ---------------------------------------------------------------------------
extern "C" void kernel_launch(void* const* d_in, const int* in_sizes, int n_in,
                              void* d_out, int out_size) {
    const float* x  = (const float*)d_in[0];
    const float* S  = (const float*)d_in[1];
    const float* Wk = (const float*)d_in[2];
    const float* Wv = (const float*)d_in[3];
    const float* Wq = (const float*)d_in[4];
    const float* Wa = (const float*)d_in[5];
    const float* da = (const float*)d_in[6];
    const float* ba = (const float*)d_in[7];
    float* out = (float*)d_out;

    cudaFuncSetAttribute(proj_gemm_mma, cudaFuncAttributeMaxDynamicSharedMemorySize, GEMM_SMEM);

    prep_w<<<256, 256>>>(Wk, Wq, Wv, Wa);
    proj_gemm_mma<<<M_TOT / 128, 512, GEMM_SMEM>>>(x);
    kk_kernel<<<M_TOT / 128, 128>>>();
    scan_kernel<<<BATCH * 16, 128>>>(S, da, ba, out);
}

// round 16
// speedup vs baseline: 1.2268x; 1.2268x over previous
#include <cuda_runtime.h>
#include <cuda_bf16.h>
#include <cstdint>

#define T_STEPS 512
#define BATCH   32
#define DIM     1024
#define NS      64
#define M_TOT   (T_STEPS * BATCH)   // 16384

// ---------------------------------------------------------------------------
// Device scratch
// ---------------------------------------------------------------------------
__device__ __align__(16) float  g_proj[(size_t)M_TOT * 256];   // [m][{k,q,v,ax}x64]
__device__ __align__(16) float  g_kk8[(size_t)M_TOT * 8];      // k_t·k_{t+1..8}
__device__ __align__(16) __nv_bfloat16 g_Wh[256 * DIM];        // rows: k,q,v,ax
__device__ __align__(16) __nv_bfloat16 g_Wl[256 * DIM];

// ---------------------------------------------------------------------------
// helpers
// ---------------------------------------------------------------------------
__device__ __forceinline__ uint32_t smem_u32(const void* p) {
    uint32_t a;
    asm("{ .reg .u64 t; cvta.to.shared.u64 t, %1; cvt.u32.u64 %0, t; }" : "=r"(a) : "l"(p));
    return a;
}
__device__ __forceinline__ uint32_t bfpack(float hi_elem, float lo_elem) {
    uint32_t r;
    asm("cvt.rn.bf16x2.f32 %0, %1, %2;" : "=r"(r) : "f"(hi_elem), "f"(lo_elem));
    return r;
}
__device__ __forceinline__ uint32_t swoff(int row, int unit) {
    return (uint32_t)(row * 64 + ((unit ^ ((row >> 1) & 3)) << 4));
}
__device__ __forceinline__ void cp16(uint32_t dst, const void* src) {
    asm volatile("cp.async.cg.shared.global [%0], [%1], 16;" :: "r"(dst), "l"(src) : "memory");
}
__device__ __forceinline__ void ldsm4(uint32_t* r, uint32_t a) {
    asm volatile("ldmatrix.sync.aligned.m8n8.x4.shared.b16 {%0,%1,%2,%3}, [%4];"
                 : "=r"(r[0]), "=r"(r[1]), "=r"(r[2]), "=r"(r[3]) : "r"(a));
}
__device__ __forceinline__ void ldsm2(uint32_t* r, uint32_t a) {
    asm volatile("ldmatrix.sync.aligned.m8n8.x2.shared.b16 {%0,%1}, [%2];"
                 : "=r"(r[0]), "=r"(r[1]) : "r"(a));
}
__device__ __forceinline__ void mma16816(float* c, const uint32_t* a, const uint32_t* b) {
    asm volatile(
        "mma.sync.aligned.m16n8k16.row.col.f32.bf16.bf16.f32 "
        "{%0,%1,%2,%3}, {%4,%5,%6,%7}, {%8,%9}, {%0,%1,%2,%3};"
        : "+f"(c[0]), "+f"(c[1]), "+f"(c[2]), "+f"(c[3])
        : "r"(a[0]), "r"(a[1]), "r"(a[2]), "r"(a[3]), "r"(b[0]), "r"(b[1]));
}

// ---------------------------------------------------------------------------
// Weight prep: split 4x[64,1024] fp32 into bf16 hi/lo, row order k,q,v,ax
// ---------------------------------------------------------------------------
__global__ __launch_bounds__(256) void prep_w(
    const float* __restrict__ Wk, const float* __restrict__ Wq,
    const float* __restrict__ Wv, const float* __restrict__ Wa)
{
    int idx = blockIdx.x * 256 + threadIdx.x;
    int r = idx >> 8, c4 = idx & 255;
    const float* W = (r < 64) ? Wk : (r < 128) ? Wq : (r < 192) ? Wv : Wa;
    float4 v = ((const float4*)(W + (size_t)(r & 63) * DIM))[c4];
    uint32_t h01 = bfpack(v.y, v.x);
    uint32_t h23 = bfpack(v.w, v.z);
    float l0 = v.x - __uint_as_float(h01 << 16);
    float l1 = v.y - __uint_as_float(h01 & 0xffff0000u);
    float l2 = v.z - __uint_as_float(h23 << 16);
    float l3 = v.w - __uint_as_float(h23 & 0xffff0000u);
    ((uint2*)g_Wh)[idx] = make_uint2(h01, h23);
    ((uint2*)g_Wl)[idx] = make_uint2(bfpack(l1, l0), bfpack(l3, l2));
}

// ---------------------------------------------------------------------------
// Tensor-core projection GEMM (mma.sync bf16x3) — unchanged (passing since R7)
// ---------------------------------------------------------------------------
#define STAGE_BYTES 49152
#define GEMM_SMEM   (2 * STAGE_BYTES)

__global__ __launch_bounds__(512) void proj_gemm_mma(const float* __restrict__ X)
{
    extern __shared__ char sm[];
    const uint32_t sb = smem_u32(sm);
    const int tid  = threadIdx.x;
    const int lane = tid & 31;
    const int wid  = tid >> 5;
    const int wm   = wid & 3;
    const int wn   = wid >> 2;
    const int m0   = blockIdx.x * 128;

    float c[2][8][4];
    #pragma unroll
    for (int i = 0; i < 2; i++)
        #pragma unroll
        for (int j = 0; j < 8; j++)
            #pragma unroll
            for (int q = 0; q < 4; q++) c[i][j][q] = 0.f;

    const int xrow = tid >> 2, xu = tid & 3;
    const int wp   = tid >> 8, wrow = tid & 255;

    auto issueW = [&](int ch, int s) {
        const __nv_bfloat16* src = (wp ? g_Wl : g_Wh) + (size_t)wrow * DIM + ch * 32;
        uint32_t dbase = sb + s * STAGE_BYTES + 16384 + wp * 16384;
        #pragma unroll
        for (int u = 0; u < 4; u++) cp16(dbase + swoff(wrow, u), src + u * 8);
        asm volatile("cp.async.commit_group;" ::: "memory");
    };
    float4 xa, xb;
    auto loadX = [&](int ch) {
        const float* p = X + (size_t)(m0 + xrow) * DIM + ch * 32 + xu * 8;
        xa = *(const float4*)p;
        xb = *(const float4*)(p + 4);
    };
    auto stsX = [&](int s) {
        uint32_t h01 = bfpack(xa.y, xa.x), h23 = bfpack(xa.w, xa.z);
        uint32_t h45 = bfpack(xb.y, xb.x), h67 = bfpack(xb.w, xb.z);
        float l0 = xa.x - __uint_as_float(h01 << 16);
        float l1 = xa.y - __uint_as_float(h01 & 0xffff0000u);
        float l2 = xa.z - __uint_as_float(h23 << 16);
        float l3 = xa.w - __uint_as_float(h23 & 0xffff0000u);
        float l4 = xb.x - __uint_as_float(h45 << 16);
        float l5 = xb.y - __uint_as_float(h45 & 0xffff0000u);
        float l6 = xb.z - __uint_as_float(h67 << 16);
        float l7 = xb.w - __uint_as_float(h67 & 0xffff0000u);
        uint32_t off = s * STAGE_BYTES + swoff(xrow, xu);
        *(uint4*)(sm + off)        = make_uint4(h01, h23, h45, h67);
        *(uint4*)(sm + off + 8192) = make_uint4(bfpack(l1, l0), bfpack(l3, l2),
                                                bfpack(l5, l4), bfpack(l7, l6));
    };

    issueW(0, 0);
    loadX(0);

    for (int ch = 0; ch < 32; ch++) {
        const int s = ch & 1;
        asm volatile("cp.async.wait_group 0;" ::: "memory");
        stsX(s);
        if (ch + 1 < 32) { issueW(ch + 1, s ^ 1); loadX(ch + 1); }
        __syncthreads();

        const uint32_t st = sb + s * STAGE_BYTES;
        #pragma unroll
        for (int kt = 0; kt < 2; kt++) {
            uint32_t ah[2][4], al[2][4];
            #pragma unroll
            for (int mt = 0; mt < 2; mt++) {
                uint32_t aoff = swoff(wm * 32 + mt * 16 + (lane & 15), kt * 2 + (lane >> 4));
                ldsm4(ah[mt], st + aoff);
                ldsm4(al[mt], st + 8192 + aoff);
            }
            #pragma unroll
            for (int nt = 0; nt < 8; nt++) {
                uint32_t boff = swoff(wn * 64 + nt * 8 + (lane & 7),
                                      kt * 2 + ((lane >> 3) & 1));
                uint32_t bh[2], bl[2];
                ldsm2(bh, st + 16384 + boff);
                ldsm2(bl, st + 32768 + boff);
                mma16816(c[0][nt], ah[0], bh);
                mma16816(c[1][nt], ah[1], bh);
                mma16816(c[0][nt], al[0], bh);
                mma16816(c[1][nt], al[1], bh);
                mma16816(c[0][nt], ah[0], bl);
                mma16816(c[1][nt], ah[1], bl);
            }
        }
        __syncthreads();
    }

    #pragma unroll
    for (int mt = 0; mt < 2; mt++) {
        #pragma unroll
        for (int nt = 0; nt < 8; nt++) {
            int m = m0 + wm * 32 + mt * 16 + (lane >> 2);
            int n = wn * 64 + nt * 8 + (lane & 3) * 2;
            *(float2*)&g_proj[(size_t)m * 256 + n]       = make_float2(c[mt][nt][0], c[mt][nt][1]);
            *(float2*)&g_proj[(size_t)(m + 8) * 256 + n] = make_float2(c[mt][nt][2], c[mt][nt][3]);
        }
    }
}

// ---------------------------------------------------------------------------
// kk8 kernel: g_kk8[t][b][j-1] = k_t · k_{t+j}, j = 1..8 (0 past the end)
// ---------------------------------------------------------------------------
__global__ __launch_bounds__(128) void kk8_kernel()
{
    int idx = blockIdx.x * 128 + threadIdx.x;      // 0..16383
    int t = idx >> 5, b = idx & 31;
    const float4* p0 = (const float4*)(g_proj + (size_t)(t * 32 + b) * 256);
    float4 k0[16];
    #pragma unroll
    for (int i = 0; i < 16; i++) k0[i] = p0[i];
    float res[8];
    #pragma unroll
    for (int j = 1; j <= 8; j++) {
        int tj = t + j; if (tj > T_STEPS - 1) tj = T_STEPS - 1;
        const float4* pj = (const float4*)(g_proj + (size_t)(tj * 32 + b) * 256);
        float a = 0.f;
        #pragma unroll
        for (int i = 0; i < 16; i++) {
            float4 kj = pj[i];
            a += k0[i].x * kj.x + k0[i].y * kj.y + k0[i].z * kj.z + k0[i].w * kj.w;
        }
        res[j - 1] = (t + j <= T_STEPS - 1) ? a : 0.f;
    }
    float4* dst = (float4*)(g_kk8 + (size_t)idx * 8);
    dst[0] = make_float4(res[0], res[1], res[2], res[3]);
    dst[1] = make_float4(res[4], res[5], res[6], res[7]);
}

// ---------------------------------------------------------------------------
// Scan v8: depth-8 sigma-affine lookahead; dots batched 4-per-4-steps,
// h-reductions batched 8-per-block -> all butterflies pipelined, no serial
// shuffle stalls inside the step loop.
// Config (R13 sweet spot): warp = 2 rows x 16 lanes (4 cols/lane),
// CTA = 8 rows (128 thr), grid 256. cp.async block staging, LDS steady state.
// smem floats: k 4x512 | q 2x512 | kk 2x64 | v 2x64 | ax 2x64  = 3456
// ---------------------------------------------------------------------------
#define SMK   0
#define SMQ   2048
#define SMKK  3072
#define SMV   3200
#define SMAX  3328
#define SMTOT 3456

__global__ __launch_bounds__(128) void scan_kernel(
    const float* __restrict__ S_in,
    const float* __restrict__ d_alpha,
    const float* __restrict__ b_alpha,
    float* __restrict__ out)
{
    __shared__ __align__(16) float sms[SMTOT];

    const int tid  = threadIdx.x;
    const int lane = tid & 31;
    const int w    = tid >> 5;
    const int half = lane >> 4;
    const int sub  = lane & 15;
    const int b    = blockIdx.x >> 3;
    const int rg   = blockIdx.x & 7;
    const int r0   = rg * 8;
    const int wr   = w * 2 + half;      // row within CTA (0..7)
    const int row  = r0 + wr;
    const int c0   = sub * 4;

    const uint32_t smb = smem_u32(sms);

    auto issue = [&](int B) {
        {   // k(B+3) -> slot (B+3)&3 ; 128 cp16
            int ks = (B + 3) & 3;
            int tb = (B + 3) * 8;
            int t = tid >> 4, u = tid & 15;
            int gt = tb + t; if (gt > T_STEPS - 1) gt = T_STEPS - 1;
            cp16(smb + (uint32_t)(SMK + ks * 512 + t * 64 + u * 4) * 4,
                 g_proj + ((size_t)(gt * 32 + b)) * 256 + u * 4);
        }
        if (B >= -1) {
            int ss = (B + 1) & 1;
            int tb = (B + 1) * 8;
            {   // q(B+1)
                int t = tid >> 4, u = tid & 15;
                int gt = tb + t; if (gt > T_STEPS - 1) gt = T_STEPS - 1;
                cp16(smb + (uint32_t)(SMQ + ss * 512 + t * 64 + u * 4) * 4,
                     g_proj + ((size_t)(gt * 32 + b)) * 256 + 64 + u * 4);
            }
            if (tid < 16) {          // kk(B+1): 8 floats per step
                int t = tid >> 1, hf = tid & 1;
                int gt = tb + t; if (gt > T_STEPS - 1) gt = T_STEPS - 1;
                cp16(smb + (uint32_t)(SMKK + ss * 64 + t * 8 + hf * 4) * 4,
                     g_kk8 + (size_t)(gt * 32 + b) * 8 + hf * 4);
            } else if (tid < 32) {   // v(B+1): 8 rows per step
                int i = tid - 16, t = i >> 1, hf = i & 1;
                int gt = tb + t; if (gt > T_STEPS - 1) gt = T_STEPS - 1;
                cp16(smb + (uint32_t)(SMV + ss * 64 + t * 8 + hf * 4) * 4,
                     g_proj + ((size_t)(gt * 32 + b)) * 256 + 128 + r0 + hf * 4);
            } else if (tid < 48) {   // ax(B+1), pre-shifted +1
                int i = tid - 32, t = i >> 1, hf = i & 1;
                int gt = tb + t + 1; if (gt > T_STEPS - 1) gt = T_STEPS - 1;
                cp16(smb + (uint32_t)(SMAX + ss * 64 + t * 8 + hf * 4) * 4,
                     g_proj + ((size_t)(gt * 32 + b)) * 256 + 192 + r0 + hf * 4);
            }
        }
        asm volatile("cp.async.commit_group;" ::: "memory");
    };

    issue(-3);   // k(0)
    issue(-2);   // k(1)
    issue(-1);   // k(2) + q(0) + scal(0)
    asm volatile("cp.async.wait_group 0;" ::: "memory");
    __syncthreads();

    float S0, S1, S2, S3;
    {
        const float4 sv = *(const float4*)(S_in + ((size_t)b * NS + row) * NS + c0);
        S0 = sv.x; S1 = sv.y; S2 = sv.z; S3 = sv.w;
    }
    const float da = d_alpha[row];
    const float ba = b_alpha[row];

    auto red16 = [](float v) {
        v += __shfl_xor_sync(0xffffffffu, v, 1);
        v += __shfl_xor_sync(0xffffffffu, v, 2);
        v += __shfl_xor_sync(0xffffffffu, v, 4);
        v += __shfl_xor_sync(0xffffffffu, v, 8);
        return v;
    };

    // Prologue: 9 dots of S_init with k_0..k_8
    float x, A1, A2, A3, A4, B0, B1, B2, B3;
    {
        float dv[9];
        #pragma unroll
        for (int j = 0; j < 9; j++) {
            const float4 kv = *(const float4*)(sms + SMK + (j >> 3) * 512 + (j & 7) * 64 + c0);
            dv[j] = fmaf(S3, kv.w, fmaf(S2, kv.z, fmaf(S1, kv.y, S0 * kv.x)));
        }
        #pragma unroll
        for (int lev = 1; lev <= 8; lev <<= 1) {
            float e[9];
            #pragma unroll
            for (int j = 0; j < 9; j++) e[j] = __shfl_xor_sync(0xffffffffu, dv[j], lev);
            #pragma unroll
            for (int j = 0; j < 9; j++) dv[j] += e[j];
        }
        float ax0 = g_proj[(size_t)b * 256 + 192 + row] + ba;
        x = fmaf(da, dv[0], ax0);
        A1 = dv[1]; A2 = dv[2]; A3 = dv[3]; A4 = dv[4];
        B0 = dv[5]; B1 = dv[6]; B2 = dv[7]; B3 = dv[8];
    }

    for (int B = 0; B < 64; B++) {
        __syncthreads();
        issue(B);                                          // k(B+3), q(B+1), scal(B+1)
        asm volatile("cp.async.wait_group 1;" ::: "memory");
        __syncthreads();

        const float* kb  = sms + SMK + (B & 3) * 512;
        const float* qb  = sms + SMQ + (B & 1) * 512;
        const float* kkb = sms + SMKK + (B & 1) * 64;
        const float* vb  = sms + SMV + (B & 1) * 64;
        const float* axb = sms + SMAX + (B & 1) * 64;

        float hpart[8];

        #pragma unroll
        for (int t = 0; t < 8; t++) {
            const int p = t & 3;
            float4 kv  = *(const float4*)(kb + t * 64 + c0);
            float4 qv  = *(const float4*)(qb + t * 64 + c0);
            float4 kkA = *(const float4*)(kkb + t * 8);       // depths 1..4
            float4 kkB = *(const float4*)(kkb + t * 8 + 4);   // depths 5..8
            const float vc  = vb[t * 8 + wr];
            const float axn = axb[t * 8 + wr] + ba;           // ax_{s+1}

            // ---- pre-sigma ----
            float vk1 = vc * kkA.x, vk2 = vc * kkA.y, vk3 = vc * kkA.z, vk4 = vc * kkA.w;
            float vk5 = vc * kkB.x, vk6 = vc * kkB.y, vk7 = vc * kkB.z, vk8 = vc * kkB.w;
            float px  = da * (A1 - vk1);
            float qx  = fmaf(da, vk1, axn);
            float uA2 = A2 - vk2, uA3 = A3 - vk3, uA4 = A4 - vk4;
            float uB0 = 0.f, uB1 = 0.f, uB2 = 0.f, uB3 = 0.f;
            if (p == 0) { uB0 = B0 - vk5; uB1 = B1 - vk6; uB2 = B2 - vk7; uB3 = B3 - vk8; }
            if (p == 1) { uB1 = B1 - vk5; uB2 = B2 - vk6; uB3 = B3 - vk7; }
            if (p == 2) { uB2 = B2 - vk5; uB3 = B3 - vk6; }
            if (p == 3) { uB3 = B3 - vk5; }
            float tj0 = vc * kv.x, tj1 = vc * kv.y, tj2 = vc * kv.z, tj3 = vc * kv.w;
            float uj0 = S0 - tj0, uj1 = S1 - tj1, uj2 = S2 - tj2, uj3 = S3 - tj3;

            // ---- critical chain: sigmoid -> 1 FMA ----
            float sg = __fdividef(1.f, 1.f + __expf(-x));
            x = fmaf(sg, px, qx);

            // ---- sigma-affine updates (no reductions here) ----
            A1 = fmaf(sg, uA2, vk2);
            A2 = fmaf(sg, uA3, vk3);
            A3 = fmaf(sg, uA4, vk4);
            if (p == 0) { B0 = fmaf(sg, uB0, vk5); B1 = fmaf(sg, uB1, vk6);
                          B2 = fmaf(sg, uB2, vk7); B3 = fmaf(sg, uB3, vk8); A4 = B0; }
            if (p == 1) { B1 = fmaf(sg, uB1, vk5); B2 = fmaf(sg, uB2, vk6);
                          B3 = fmaf(sg, uB3, vk7); A4 = B1; }
            if (p == 2) { B2 = fmaf(sg, uB2, vk5); B3 = fmaf(sg, uB3, vk6); A4 = B2; }
            if (p == 3) { B3 = fmaf(sg, uB3, vk5); A4 = B3; }
            S0 = fmaf(sg, uj0, tj0);
            S1 = fmaf(sg, uj1, tj1);
            S2 = fmaf(sg, uj2, tj2);
            S3 = fmaf(sg, uj3, tj3);
            hpart[t] = fmaf(S3, qv.w, fmaf(S2, qv.z, fmaf(S1, qv.y, S0 * qv.x)));

            // ---- batched dot refill (every 4th step): S_T . k_{T+6..T+9} ----
            if (p == 3) {
                float D[4];
                #pragma unroll
                for (int i = 0; i < 4; i++) {
                    int g = 8 * B + t + 6 + i;              // global k step
                    const float4 kd = *(const float4*)(sms + SMK + ((g >> 3) & 3) * 512
                                                        + (g & 7) * 64 + c0);
                    D[i] = fmaf(S3, kd.w, fmaf(S2, kd.z, fmaf(S1, kd.y, S0 * kd.x)));
                }
                #pragma unroll
                for (int lev = 1; lev <= 8; lev <<= 1) {
                    float e0 = __shfl_xor_sync(0xffffffffu, D[0], lev);
                    float e1 = __shfl_xor_sync(0xffffffffu, D[1], lev);
                    float e2 = __shfl_xor_sync(0xffffffffu, D[2], lev);
                    float e3 = __shfl_xor_sync(0xffffffffu, D[3], lev);
                    D[0] += e0; D[1] += e1; D[2] += e2; D[3] += e3;
                }
                B0 = D[0]; B1 = D[1]; B2 = D[2]; B3 = D[3];
            }
        }

        // ---- block-end h epilogue: pipelined butterfly of 8 values ----
        #pragma unroll
        for (int lev = 1; lev <= 8; lev <<= 1) {
            float e[8];
            #pragma unroll
            for (int i = 0; i < 8; i++) e[i] = __shfl_xor_sync(0xffffffffu, hpart[i], lev);
            #pragma unroll
            for (int i = 0; i < 8; i++) hpart[i] += e[i];
        }
        if (sub == 0) {
            #pragma unroll
            for (int i = 0; i < 8; i++) {
                float h = hpart[i];
                float sh = __fdividef(1.f, 1.f + __expf(-h));
                out[(size_t)(8 * B + i) * BATCH * NS + (size_t)b * NS + row] = h * h * sh;
            }
        }
    }

    // S_final
    float* sf = out + (size_t)T_STEPS * BATCH * NS + ((size_t)b * NS + row) * NS + c0;
    *(float4*)sf = make_float4(S0, S1, S2, S3);
}

// ---------------------------------------------------------------------------
extern "C" void kernel_launch(void* const* d_in, const int* in_sizes, int n_in,
                              void* d_out, int out_size) {
    const float* x  = (const float*)d_in[0];
    const float* S  = (const float*)d_in[1];
    const float* Wk = (const float*)d_in[2];
    const float* Wv = (const float*)d_in[3];
    const float* Wq = (const float*)d_in[4];
    const float* Wa = (const float*)d_in[5];
    const float* da = (const float*)d_in[6];
    const float* ba = (const float*)d_in[7];
    float* out = (float*)d_out;

    cudaFuncSetAttribute(proj_gemm_mma, cudaFuncAttributeMaxDynamicSharedMemorySize, GEMM_SMEM);

    prep_w<<<256, 256>>>(Wk, Wq, Wv, Wa);
    proj_gemm_mma<<<M_TOT / 128, 512, GEMM_SMEM>>>(x);
    kk8_kernel<<<M_TOT / 128, 128>>>();
    scan_kernel<<<BATCH * 8, 128>>>(S, da, ba, out);
}

// round 17
// speedup vs baseline: 1.2941x; 1.0548x over previous
#include <cuda_runtime.h>
#include <cuda_bf16.h>
#include <cstdint>

#define T_STEPS 512
#define BATCH   32
#define DIM     1024
#define NS      64
#define M_TOT   (T_STEPS * BATCH)   // 16384

// ---------------------------------------------------------------------------
// Device scratch
// ---------------------------------------------------------------------------
__device__ __align__(16) float  g_proj[(size_t)M_TOT * 256];   // [m][{k,q,v,ax}x64]
__device__ __align__(16) float  g_kk8[(size_t)M_TOT * 8];      // k_t·k_{t+1..8}
__device__ __align__(16) __nv_bfloat16 g_Wh[256 * DIM];        // rows: k,q,v,ax
__device__ __align__(16) __nv_bfloat16 g_Wl[256 * DIM];

// ---------------------------------------------------------------------------
// helpers
// ---------------------------------------------------------------------------
__device__ __forceinline__ uint32_t smem_u32(const void* p) {
    uint32_t a;
    asm("{ .reg .u64 t; cvta.to.shared.u64 t, %1; cvt.u32.u64 %0, t; }" : "=r"(a) : "l"(p));
    return a;
}
__device__ __forceinline__ uint32_t bfpack(float hi_elem, float lo_elem) {
    uint32_t r;
    asm("cvt.rn.bf16x2.f32 %0, %1, %2;" : "=r"(r) : "f"(hi_elem), "f"(lo_elem));
    return r;
}
__device__ __forceinline__ uint32_t swoff(int row, int unit) {
    return (uint32_t)(row * 64 + ((unit ^ ((row >> 1) & 3)) << 4));
}
__device__ __forceinline__ void cp16(uint32_t dst, const void* src) {
    asm volatile("cp.async.cg.shared.global [%0], [%1], 16;" :: "r"(dst), "l"(src) : "memory");
}
__device__ __forceinline__ void ldsm4(uint32_t* r, uint32_t a) {
    asm volatile("ldmatrix.sync.aligned.m8n8.x4.shared.b16 {%0,%1,%2,%3}, [%4];"
                 : "=r"(r[0]), "=r"(r[1]), "=r"(r[2]), "=r"(r[3]) : "r"(a));
}
__device__ __forceinline__ void ldsm2(uint32_t* r, uint32_t a) {
    asm volatile("ldmatrix.sync.aligned.m8n8.x2.shared.b16 {%0,%1}, [%2];"
                 : "=r"(r[0]), "=r"(r[1]) : "r"(a));
}
__device__ __forceinline__ void mma16816(float* c, const uint32_t* a, const uint32_t* b) {
    asm volatile(
        "mma.sync.aligned.m16n8k16.row.col.f32.bf16.bf16.f32 "
        "{%0,%1,%2,%3}, {%4,%5,%6,%7}, {%8,%9}, {%0,%1,%2,%3};"
        : "+f"(c[0]), "+f"(c[1]), "+f"(c[2]), "+f"(c[3])
        : "r"(a[0]), "r"(a[1]), "r"(a[2]), "r"(a[3]), "r"(b[0]), "r"(b[1]));
}

// ---------------------------------------------------------------------------
// Weight prep: split 4x[64,1024] fp32 into bf16 hi/lo, row order k,q,v,ax
// ---------------------------------------------------------------------------
__global__ __launch_bounds__(256) void prep_w(
    const float* __restrict__ Wk, const float* __restrict__ Wq,
    const float* __restrict__ Wv, const float* __restrict__ Wa)
{
    int idx = blockIdx.x * 256 + threadIdx.x;
    int r = idx >> 8, c4 = idx & 255;
    const float* W = (r < 64) ? Wk : (r < 128) ? Wq : (r < 192) ? Wv : Wa;
    float4 v = ((const float4*)(W + (size_t)(r & 63) * DIM))[c4];
    uint32_t h01 = bfpack(v.y, v.x);
    uint32_t h23 = bfpack(v.w, v.z);
    float l0 = v.x - __uint_as_float(h01 << 16);
    float l1 = v.y - __uint_as_float(h01 & 0xffff0000u);
    float l2 = v.z - __uint_as_float(h23 << 16);
    float l3 = v.w - __uint_as_float(h23 & 0xffff0000u);
    ((uint2*)g_Wh)[idx] = make_uint2(h01, h23);
    ((uint2*)g_Wl)[idx] = make_uint2(bfpack(l1, l0), bfpack(l3, l2));
}

// ---------------------------------------------------------------------------
// Tensor-core projection GEMM (mma.sync bf16x3) — unchanged (passing since R7)
// ---------------------------------------------------------------------------
#define STAGE_BYTES 49152
#define GEMM_SMEM   (2 * STAGE_BYTES)

__global__ __launch_bounds__(512) void proj_gemm_mma(const float* __restrict__ X)
{
    extern __shared__ char sm[];
    const uint32_t sb = smem_u32(sm);
    const int tid  = threadIdx.x;
    const int lane = tid & 31;
    const int wid  = tid >> 5;
    const int wm   = wid & 3;
    const int wn   = wid >> 2;
    const int m0   = blockIdx.x * 128;

    float c[2][8][4];
    #pragma unroll
    for (int i = 0; i < 2; i++)
        #pragma unroll
        for (int j = 0; j < 8; j++)
            #pragma unroll
            for (int q = 0; q < 4; q++) c[i][j][q] = 0.f;

    const int xrow = tid >> 2, xu = tid & 3;
    const int wp   = tid >> 8, wrow = tid & 255;

    auto issueW = [&](int ch, int s) {
        const __nv_bfloat16* src = (wp ? g_Wl : g_Wh) + (size_t)wrow * DIM + ch * 32;
        uint32_t dbase = sb + s * STAGE_BYTES + 16384 + wp * 16384;
        #pragma unroll
        for (int u = 0; u < 4; u++) cp16(dbase + swoff(wrow, u), src + u * 8);
        asm volatile("cp.async.commit_group;" ::: "memory");
    };
    float4 xa, xb;
    auto loadX = [&](int ch) {
        const float* p = X + (size_t)(m0 + xrow) * DIM + ch * 32 + xu * 8;
        xa = *(const float4*)p;
        xb = *(const float4*)(p + 4);
    };
    auto stsX = [&](int s) {
        uint32_t h01 = bfpack(xa.y, xa.x), h23 = bfpack(xa.w, xa.z);
        uint32_t h45 = bfpack(xb.y, xb.x), h67 = bfpack(xb.w, xb.z);
        float l0 = xa.x - __uint_as_float(h01 << 16);
        float l1 = xa.y - __uint_as_float(h01 & 0xffff0000u);
        float l2 = xa.z - __uint_as_float(h23 << 16);
        float l3 = xa.w - __uint_as_float(h23 & 0xffff0000u);
        float l4 = xb.x - __uint_as_float(h45 << 16);
        float l5 = xb.y - __uint_as_float(h45 & 0xffff0000u);
        float l6 = xb.z - __uint_as_float(h67 << 16);
        float l7 = xb.w - __uint_as_float(h67 & 0xffff0000u);
        uint32_t off = s * STAGE_BYTES + swoff(xrow, xu);
        *(uint4*)(sm + off)        = make_uint4(h01, h23, h45, h67);
        *(uint4*)(sm + off + 8192) = make_uint4(bfpack(l1, l0), bfpack(l3, l2),
                                                bfpack(l5, l4), bfpack(l7, l6));
    };

    issueW(0, 0);
    loadX(0);

    for (int ch = 0; ch < 32; ch++) {
        const int s = ch & 1;
        asm volatile("cp.async.wait_group 0;" ::: "memory");
        stsX(s);
        if (ch + 1 < 32) { issueW(ch + 1, s ^ 1); loadX(ch + 1); }
        __syncthreads();

        const uint32_t st = sb + s * STAGE_BYTES;
        #pragma unroll
        for (int kt = 0; kt < 2; kt++) {
            uint32_t ah[2][4], al[2][4];
            #pragma unroll
            for (int mt = 0; mt < 2; mt++) {
                uint32_t aoff = swoff(wm * 32 + mt * 16 + (lane & 15), kt * 2 + (lane >> 4));
                ldsm4(ah[mt], st + aoff);
                ldsm4(al[mt], st + 8192 + aoff);
            }
            #pragma unroll
            for (int nt = 0; nt < 8; nt++) {
                uint32_t boff = swoff(wn * 64 + nt * 8 + (lane & 7),
                                      kt * 2 + ((lane >> 3) & 1));
                uint32_t bh[2], bl[2];
                ldsm2(bh, st + 16384 + boff);
                ldsm2(bl, st + 32768 + boff);
                mma16816(c[0][nt], ah[0], bh);
                mma16816(c[1][nt], ah[1], bh);
                mma16816(c[0][nt], al[0], bh);
                mma16816(c[1][nt], al[1], bh);
                mma16816(c[0][nt], ah[0], bl);
                mma16816(c[1][nt], ah[1], bl);
            }
        }
        __syncthreads();
    }

    #pragma unroll
    for (int mt = 0; mt < 2; mt++) {
        #pragma unroll
        for (int nt = 0; nt < 8; nt++) {
            int m = m0 + wm * 32 + mt * 16 + (lane >> 2);
            int n = wn * 64 + nt * 8 + (lane & 3) * 2;
            *(float2*)&g_proj[(size_t)m * 256 + n]       = make_float2(c[mt][nt][0], c[mt][nt][1]);
            *(float2*)&g_proj[(size_t)(m + 8) * 256 + n] = make_float2(c[mt][nt][2], c[mt][nt][3]);
        }
    }
}

// ---------------------------------------------------------------------------
// kk8 v2 (coalesced): one CTA per (b, 16-step window). Stage k rows
// t0..t0+23 for batch b into smem (coalesced, each row read once per CTA),
// then thread (tl, j) computes k_{t0+tl} . k_{t0+tl+j} from smem.
// Row stride padded to 68 floats to avoid bank alignment conflicts.
// ---------------------------------------------------------------------------
__global__ __launch_bounds__(128) void kk8_kernel()
{
    __shared__ __align__(16) float sk[24][68];

    const int tid = threadIdx.x;
    const int b   = blockIdx.x & 31;
    const int t0  = (blockIdx.x >> 5) * 16;

    #pragma unroll
    for (int i = tid; i < 24 * 16; i += 128) {
        int r = i >> 4, u = i & 15;
        int gt = t0 + r; if (gt > T_STEPS - 1) gt = T_STEPS - 1;
        *(float4*)&sk[r][u * 4] =
            *(const float4*)(g_proj + ((size_t)(gt * 32 + b)) * 256 + u * 4);
    }
    __syncthreads();

    const int tl = tid >> 3;          // 0..15
    const int j  = (tid & 7) + 1;     // 1..8
    float a = 0.f;
    #pragma unroll
    for (int u = 0; u < 16; u++) {
        float4 x0 = *(const float4*)&sk[tl][u * 4];
        float4 xj = *(const float4*)&sk[tl + j][u * 4];
        a = fmaf(x0.x, xj.x, a);
        a = fmaf(x0.y, xj.y, a);
        a = fmaf(x0.z, xj.z, a);
        a = fmaf(x0.w, xj.w, a);
    }
    const int t = t0 + tl;
    if (t + j > T_STEPS - 1) a = 0.f;
    g_kk8[(size_t)(t * 32 + b) * 8 + (j - 1)] = a;
}

// ---------------------------------------------------------------------------
// Scan v8 (unchanged from R16 — 78.0us, validated): depth-8 sigma-affine
// lookahead; dots batched 4-per-4-steps, h-reductions batched 8-per-block.
// warp = 2 rows x 16 lanes (4 cols/lane), CTA = 8 rows (128 thr), grid 256.
// smem floats: k 4x512 | q 2x512 | kk 2x64 | v 2x64 | ax 2x64  = 3456
// ---------------------------------------------------------------------------
#define SMK   0
#define SMQ   2048
#define SMKK  3072
#define SMV   3200
#define SMAX  3328
#define SMTOT 3456

__global__ __launch_bounds__(128) void scan_kernel(
    const float* __restrict__ S_in,
    const float* __restrict__ d_alpha,
    const float* __restrict__ b_alpha,
    float* __restrict__ out)
{
    __shared__ __align__(16) float sms[SMTOT];

    const int tid  = threadIdx.x;
    const int lane = tid & 31;
    const int w    = tid >> 5;
    const int half = lane >> 4;
    const int sub  = lane & 15;
    const int b    = blockIdx.x >> 3;
    const int rg   = blockIdx.x & 7;
    const int r0   = rg * 8;
    const int wr   = w * 2 + half;      // row within CTA (0..7)
    const int row  = r0 + wr;
    const int c0   = sub * 4;

    const uint32_t smb = smem_u32(sms);

    auto issue = [&](int B) {
        {   // k(B+3) -> slot (B+3)&3 ; 128 cp16
            int ks = (B + 3) & 3;
            int tb = (B + 3) * 8;
            int t = tid >> 4, u = tid & 15;
            int gt = tb + t; if (gt > T_STEPS - 1) gt = T_STEPS - 1;
            cp16(smb + (uint32_t)(SMK + ks * 512 + t * 64 + u * 4) * 4,
                 g_proj + ((size_t)(gt * 32 + b)) * 256 + u * 4);
        }
        if (B >= -1) {
            int ss = (B + 1) & 1;
            int tb = (B + 1) * 8;
            {   // q(B+1)
                int t = tid >> 4, u = tid & 15;
                int gt = tb + t; if (gt > T_STEPS - 1) gt = T_STEPS - 1;
                cp16(smb + (uint32_t)(SMQ + ss * 512 + t * 64 + u * 4) * 4,
                     g_proj + ((size_t)(gt * 32 + b)) * 256 + 64 + u * 4);
            }
            if (tid < 16) {          // kk(B+1): 8 floats per step
                int t = tid >> 1, hf = tid & 1;
                int gt = tb + t; if (gt > T_STEPS - 1) gt = T_STEPS - 1;
                cp16(smb + (uint32_t)(SMKK + ss * 64 + t * 8 + hf * 4) * 4,
                     g_kk8 + (size_t)(gt * 32 + b) * 8 + hf * 4);
            } else if (tid < 32) {   // v(B+1): 8 rows per step
                int i = tid - 16, t = i >> 1, hf = i & 1;
                int gt = tb + t; if (gt > T_STEPS - 1) gt = T_STEPS - 1;
                cp16(smb + (uint32_t)(SMV + ss * 64 + t * 8 + hf * 4) * 4,
                     g_proj + ((size_t)(gt * 32 + b)) * 256 + 128 + r0 + hf * 4);
            } else if (tid < 48) {   // ax(B+1), pre-shifted +1
                int i = tid - 32, t = i >> 1, hf = i & 1;
                int gt = tb + t + 1; if (gt > T_STEPS - 1) gt = T_STEPS - 1;
                cp16(smb + (uint32_t)(SMAX + ss * 64 + t * 8 + hf * 4) * 4,
                     g_proj + ((size_t)(gt * 32 + b)) * 256 + 192 + r0 + hf * 4);
            }
        }
        asm volatile("cp.async.commit_group;" ::: "memory");
    };

    issue(-3);   // k(0)
    issue(-2);   // k(1)
    issue(-1);   // k(2) + q(0) + scal(0)
    asm volatile("cp.async.wait_group 0;" ::: "memory");
    __syncthreads();

    float S0, S1, S2, S3;
    {
        const float4 sv = *(const float4*)(S_in + ((size_t)b * NS + row) * NS + c0);
        S0 = sv.x; S1 = sv.y; S2 = sv.z; S3 = sv.w;
    }
    const float da = d_alpha[row];
    const float ba = b_alpha[row];

    // Prologue: 9 dots of S_init with k_0..k_8
    float x, A1, A2, A3, A4, B0, B1, B2, B3;
    {
        float dv[9];
        #pragma unroll
        for (int j = 0; j < 9; j++) {
            const float4 kv = *(const float4*)(sms + SMK + (j >> 3) * 512 + (j & 7) * 64 + c0);
            dv[j] = fmaf(S3, kv.w, fmaf(S2, kv.z, fmaf(S1, kv.y, S0 * kv.x)));
        }
        #pragma unroll
        for (int lev = 1; lev <= 8; lev <<= 1) {
            float e[9];
            #pragma unroll
            for (int j = 0; j < 9; j++) e[j] = __shfl_xor_sync(0xffffffffu, dv[j], lev);
            #pragma unroll
            for (int j = 0; j < 9; j++) dv[j] += e[j];
        }
        float ax0 = g_proj[(size_t)b * 256 + 192 + row] + ba;
        x = fmaf(da, dv[0], ax0);
        A1 = dv[1]; A2 = dv[2]; A3 = dv[3]; A4 = dv[4];
        B0 = dv[5]; B1 = dv[6]; B2 = dv[7]; B3 = dv[8];
    }

    for (int B = 0; B < 64; B++) {
        __syncthreads();
        issue(B);                                          // k(B+3), q(B+1), scal(B+1)
        asm volatile("cp.async.wait_group 1;" ::: "memory");
        __syncthreads();

        const float* kb  = sms + SMK + (B & 3) * 512;
        const float* qb  = sms + SMQ + (B & 1) * 512;
        const float* kkb = sms + SMKK + (B & 1) * 64;
        const float* vb  = sms + SMV + (B & 1) * 64;
        const float* axb = sms + SMAX + (B & 1) * 64;

        float hpart[8];

        #pragma unroll
        for (int t = 0; t < 8; t++) {
            const int p = t & 3;
            float4 kv  = *(const float4*)(kb + t * 64 + c0);
            float4 qv  = *(const float4*)(qb + t * 64 + c0);
            float4 kkA = *(const float4*)(kkb + t * 8);       // depths 1..4
            float4 kkB = *(const float4*)(kkb + t * 8 + 4);   // depths 5..8
            const float vc  = vb[t * 8 + wr];
            const float axn = axb[t * 8 + wr] + ba;           // ax_{s+1}

            // ---- pre-sigma ----
            float vk1 = vc * kkA.x, vk2 = vc * kkA.y, vk3 = vc * kkA.z, vk4 = vc * kkA.w;
            float vk5 = vc * kkB.x, vk6 = vc * kkB.y, vk7 = vc * kkB.z, vk8 = vc * kkB.w;
            float px  = da * (A1 - vk1);
            float qx  = fmaf(da, vk1, axn);
            float uA2 = A2 - vk2, uA3 = A3 - vk3, uA4 = A4 - vk4;
            float uB0 = 0.f, uB1 = 0.f, uB2 = 0.f, uB3 = 0.f;
            if (p == 0) { uB0 = B0 - vk5; uB1 = B1 - vk6; uB2 = B2 - vk7; uB3 = B3 - vk8; }
            if (p == 1) { uB1 = B1 - vk5; uB2 = B2 - vk6; uB3 = B3 - vk7; }
            if (p == 2) { uB2 = B2 - vk5; uB3 = B3 - vk6; }
            if (p == 3) { uB3 = B3 - vk5; }
            float tj0 = vc * kv.x, tj1 = vc * kv.y, tj2 = vc * kv.z, tj3 = vc * kv.w;
            float uj0 = S0 - tj0, uj1 = S1 - tj1, uj2 = S2 - tj2, uj3 = S3 - tj3;

            // ---- critical chain: sigmoid -> 1 FMA ----
            float sg = __fdividef(1.f, 1.f + __expf(-x));
            x = fmaf(sg, px, qx);

            // ---- sigma-affine updates (no reductions here) ----
            A1 = fmaf(sg, uA2, vk2);
            A2 = fmaf(sg, uA3, vk3);
            A3 = fmaf(sg, uA4, vk4);
            if (p == 0) { B0 = fmaf(sg, uB0, vk5); B1 = fmaf(sg, uB1, vk6);
                          B2 = fmaf(sg, uB2, vk7); B3 = fmaf(sg, uB3, vk8); A4 = B0; }
            if (p == 1) { B1 = fmaf(sg, uB1, vk5); B2 = fmaf(sg, uB2, vk6);
                          B3 = fmaf(sg, uB3, vk7); A4 = B1; }
            if (p == 2) { B2 = fmaf(sg, uB2, vk5); B3 = fmaf(sg, uB3, vk6); A4 = B2; }
            if (p == 3) { B3 = fmaf(sg, uB3, vk5); A4 = B3; }
            S0 = fmaf(sg, uj0, tj0);
            S1 = fmaf(sg, uj1, tj1);
            S2 = fmaf(sg, uj2, tj2);
            S3 = fmaf(sg, uj3, tj3);
            hpart[t] = fmaf(S3, qv.w, fmaf(S2, qv.z, fmaf(S1, qv.y, S0 * qv.x)));

            // ---- batched dot refill (every 4th step): S_T . k_{T+6..T+9} ----
            if (p == 3) {
                float D[4];
                #pragma unroll
                for (int i = 0; i < 4; i++) {
                    int g = 8 * B + t + 6 + i;              // global k step
                    const float4 kd = *(const float4*)(sms + SMK + ((g >> 3) & 3) * 512
                                                        + (g & 7) * 64 + c0);
                    D[i] = fmaf(S3, kd.w, fmaf(S2, kd.z, fmaf(S1, kd.y, S0 * kd.x)));
                }
                #pragma unroll
                for (int lev = 1; lev <= 8; lev <<= 1) {
                    float e0 = __shfl_xor_sync(0xffffffffu, D[0], lev);
                    float e1 = __shfl_xor_sync(0xffffffffu, D[1], lev);
                    float e2 = __shfl_xor_sync(0xffffffffu, D[2], lev);
                    float e3 = __shfl_xor_sync(0xffffffffu, D[3], lev);
                    D[0] += e0; D[1] += e1; D[2] += e2; D[3] += e3;
                }
                B0 = D[0]; B1 = D[1]; B2 = D[2]; B3 = D[3];
            }
        }

        // ---- block-end h epilogue: pipelined butterfly of 8 values ----
        #pragma unroll
        for (int lev = 1; lev <= 8; lev <<= 1) {
            float e[8];
            #pragma unroll
            for (int i = 0; i < 8; i++) e[i] = __shfl_xor_sync(0xffffffffu, hpart[i], lev);
            #pragma unroll
            for (int i = 0; i < 8; i++) hpart[i] += e[i];
        }
        if (sub == 0) {
            #pragma unroll
            for (int i = 0; i < 8; i++) {
                float h = hpart[i];
                float sh = __fdividef(1.f, 1.f + __expf(-h));
                out[(size_t)(8 * B + i) * BATCH * NS + (size_t)b * NS + row] = h * h * sh;
            }
        }
    }

    // S_final
    float* sf = out + (size_t)T_STEPS * BATCH * NS + ((size_t)b * NS + row) * NS + c0;
    *(float4*)sf = make_float4(S0, S1, S2, S3);
}

// ---------------------------------------------------------------------------
extern "C" void kernel_launch(void* const* d_in, const int* in_sizes, int n_in,
                              void* d_out, int out_size) {
    const float* x  = (const float*)d_in[0];
    const float* S  = (const float*)d_in[1];
    const float* Wk = (const float*)d_in[2];
    const float* Wv = (const float*)d_in[3];
    const float* Wq = (const float*)d_in[4];
    const float* Wa = (const float*)d_in[5];
    const float* da = (const float*)d_in[6];
    const float* ba = (const float*)d_in[7];
    float* out = (float*)d_out;

    cudaFuncSetAttribute(proj_gemm_mma, cudaFuncAttributeMaxDynamicSharedMemorySize, GEMM_SMEM);

    prep_w<<<256, 256>>>(Wk, Wq, Wv, Wa);
    proj_gemm_mma<<<M_TOT / 128, 512, GEMM_SMEM>>>(x);
    kk8_kernel<<<(T_STEPS / 16) * BATCH, 128>>>();
    scan_kernel<<<BATCH * 8, 128>>>(S, da, ba, out);
}